// round 5
// baseline (speedup 1.0000x reference)
#include <cuda_runtime.h>

// out[row] = alpha(||p||, ||p*w||) * (p*w), alpha folding expmap0 ->
// mobius diag -> project -> logmap0.
// Persistent grid-stride: weights loaded into registers ONCE per warp and
// reused across ~110 rows; removes 1/3 of load instructions + L1 traffic.

#define NCOLS 512
#define WARPS_PER_BLOCK 8
#define PERSISTENT_BLOCKS (148 * 8)

__device__ __forceinline__ float fast_tanh_pos(float x)
{
    float t = __expf(-2.0f * x);
    return __fdividef(1.0f - t, 1.0f + t);
}

__device__ __forceinline__ float fast_atanh01(float x)
{
    return 0.5f * __logf(__fdividef(1.0f + x, 1.0f - x));
}

__device__ __forceinline__ float row_alpha(float s1, float s2)
{
    const float SQRT_C = 0.1f;
    const float EPS    = 1e-5f;
    const float MIN_N  = 1e-5f;

    float n1 = sqrtf(s1);                 // ||p||
    float n2 = sqrtf(s2);                 // ||p*w||

    // expmap0: x = s * p
    float u_norm = fmaxf(n1, MIN_N);
    float su = SQRT_C * u_norm;
    float s = __fdividef(fast_tanh_pos(su), su);

    // mobius diag scaling
    float x_norm  = fmaxf(s * n1, MIN_N);
    float mx_norm = s * n2;               // NOT clamped (matches torch)
    float cx = fminf(fmaxf(SQRT_C * x_norm, -1.0f + EPS), 1.0f - EPS);
    float at = fast_atanh01(cx);
    float tn = fast_tanh_pos(__fdividef(mx_norm, x_norm) * at);
    float beta = __fdividef(tn * s, mx_norm * SQRT_C);  // res = beta*(p*w)
    float res_norm = tn * (1.0f / SQRT_C);              // ||res||

    // project
    float rn = fmaxf(res_norm, MIN_N);
    float maxnorm = (1.0f - 0.001f) / SQRT_C;
    float gamma = (rn > maxnorm) ? __fdividef(maxnorm, rn) : 1.0f;

    // logmap0
    float y_norm = fmaxf(gamma * res_norm, MIN_N);
    float cy = fminf(fmaxf(SQRT_C * y_norm, -1.0f + EPS), 1.0f - EPS);
    float at2 = fast_atanh01(cy);
    return __fdividef(gamma * beta * at2, y_norm * SQRT_C);
}

__global__ __launch_bounds__(WARPS_PER_BLOCK * 32)
void hyp_adapter_kernel(const float* __restrict__ params,
                        const float* __restrict__ weights,
                        float* __restrict__ out,
                        int nrows)
{
    const int warp_id = (blockIdx.x * (WARPS_PER_BLOCK * 32) + threadIdx.x) >> 5;
    const int lane = threadIdx.x & 31;
    const int nwarps = gridDim.x * WARPS_PER_BLOCK;

    // Load the invariant weight vector ONCE into registers.
    const float4* __restrict__ w4 = reinterpret_cast<const float4*>(weights);
    float4 wv[4];
#pragma unroll
    for (int j = 0; j < 4; ++j) wv[j] = __ldg(&w4[j * 32 + lane]);

    for (int row = warp_id; row < nrows; row += nwarps) {
        const float4* __restrict__ prow = reinterpret_cast<const float4*>(params) +
                                          (size_t)row * (NCOLS / 4);
        float4 m[4];
        float s1 = 0.0f, s2 = 0.0f;

#pragma unroll
        for (int j = 0; j < 4; ++j) {
            float4 a = prow[j * 32 + lane];
            s1 = fmaf(a.x, a.x, s1);
            s1 = fmaf(a.y, a.y, s1);
            s1 = fmaf(a.z, a.z, s1);
            s1 = fmaf(a.w, a.w, s1);
            m[j].x = a.x * wv[j].x;
            m[j].y = a.y * wv[j].y;
            m[j].z = a.z * wv[j].z;
            m[j].w = a.w * wv[j].w;
            s2 = fmaf(m[j].x, m[j].x, s2);
            s2 = fmaf(m[j].y, m[j].y, s2);
            s2 = fmaf(m[j].z, m[j].z, s2);
            s2 = fmaf(m[j].w, m[j].w, s2);
        }

#pragma unroll
        for (int off = 16; off > 0; off >>= 1) {
            s1 += __shfl_xor_sync(0xFFFFFFFFu, s1, off);
            s2 += __shfl_xor_sync(0xFFFFFFFFu, s2, off);
        }

        float alpha = row_alpha(s1, s2);

        float4* __restrict__ orow = reinterpret_cast<float4*>(out) +
                                    (size_t)row * (NCOLS / 4);
#pragma unroll
        for (int j = 0; j < 4; ++j) {
            float4 o;
            o.x = alpha * m[j].x;
            o.y = alpha * m[j].y;
            o.z = alpha * m[j].z;
            o.w = alpha * m[j].w;
            orow[j * 32 + lane] = o;
        }
    }
}

extern "C" void kernel_launch(void* const* d_in, const int* in_sizes, int n_in,
                              void* d_out, int out_size)
{
    const float* params  = (const float*)d_in[0];
    const float* weights = (const float*)d_in[1];
    float* out = (float*)d_out;

    int nrows = in_sizes[0] / NCOLS;   // 131072
    int max_blocks = (nrows + WARPS_PER_BLOCK - 1) / WARPS_PER_BLOCK;
    int blocks = PERSISTENT_BLOCKS < max_blocks ? PERSISTENT_BLOCKS : max_blocks;

    hyp_adapter_kernel<<<blocks, WARPS_PER_BLOCK * 32>>>(params, weights, out, nrows);
}

// round 6
// speedup vs baseline: 1.0878x; 1.0878x over previous
#include <cuda_runtime.h>

// out[row] = alpha(||p||, ||p*w||) * (p*w), alpha folding expmap0 ->
// mobius diag -> project -> logmap0.
// R4 structure (regs=32, occ~79%) + L2::256B prefetch hints on the
// streaming param loads to improve DRAM burst locality.

#define NCOLS 512
#define WARPS_PER_BLOCK 8

__device__ __forceinline__ float4 ldg_nc_prefetch256(const float4* p)
{
    float4 v;
    asm volatile("ld.global.nc.L2::256B.v4.f32 {%0,%1,%2,%3}, [%4];"
                 : "=f"(v.x), "=f"(v.y), "=f"(v.z), "=f"(v.w)
                 : "l"(p));
    return v;
}

__device__ __forceinline__ float fast_tanh_pos(float x)
{
    float t = __expf(-2.0f * x);
    return __fdividef(1.0f - t, 1.0f + t);
}

__device__ __forceinline__ float fast_atanh01(float x)
{
    return 0.5f * __logf(__fdividef(1.0f + x, 1.0f - x));
}

__global__ __launch_bounds__(WARPS_PER_BLOCK * 32, 8)
void hyp_adapter_kernel(const float* __restrict__ params,
                        const float* __restrict__ weights,
                        float* __restrict__ out,
                        int nrows)
{
    const int warp_global = (blockIdx.x * (WARPS_PER_BLOCK * 32) + threadIdx.x) >> 5;
    const int lane = threadIdx.x & 31;
    if (warp_global >= nrows) return;

    const float4* __restrict__ prow = reinterpret_cast<const float4*>(params) +
                                      (size_t)warp_global * (NCOLS / 4);
    const float4* __restrict__ w4 = reinterpret_cast<const float4*>(weights);

    float4 m[4];               // p*w — only vector state held through the tail
    float s1 = 0.0f;           // sum p^2
    float s2 = 0.0f;           // sum (p*w)^2

#pragma unroll
    for (int j = 0; j < 4; ++j) {
        float4 a = ldg_nc_prefetch256(&prow[j * 32 + lane]);
        float4 w = __ldg(&w4[j * 32 + lane]);
        s1 = fmaf(a.x, a.x, s1);
        s1 = fmaf(a.y, a.y, s1);
        s1 = fmaf(a.z, a.z, s1);
        s1 = fmaf(a.w, a.w, s1);
        m[j].x = a.x * w.x;
        m[j].y = a.y * w.y;
        m[j].z = a.z * w.z;
        m[j].w = a.w * w.w;
        s2 = fmaf(m[j].x, m[j].x, s2);
        s2 = fmaf(m[j].y, m[j].y, s2);
        s2 = fmaf(m[j].z, m[j].z, s2);
        s2 = fmaf(m[j].w, m[j].w, s2);
    }

#pragma unroll
    for (int off = 16; off > 0; off >>= 1) {
        s1 += __shfl_xor_sync(0xFFFFFFFFu, s1, off);
        s2 += __shfl_xor_sync(0xFFFFFFFFu, s2, off);
    }

    const float SQRT_C = 0.1f;
    const float EPS    = 1e-5f;
    const float MIN_N  = 1e-5f;

    float n1 = sqrtf(s1);                 // ||p||
    float n2 = sqrtf(s2);                 // ||p*w||

    // expmap0: x = s * p
    float u_norm = fmaxf(n1, MIN_N);
    float su = SQRT_C * u_norm;
    float s = __fdividef(fast_tanh_pos(su), su);

    // mobius diag scaling
    float x_norm  = fmaxf(s * n1, MIN_N);
    float mx_norm = s * n2;               // NOT clamped (matches torch)
    float cx = fminf(fmaxf(SQRT_C * x_norm, -1.0f + EPS), 1.0f - EPS);
    float at = fast_atanh01(cx);
    float tn = fast_tanh_pos(__fdividef(mx_norm, x_norm) * at);
    float beta = __fdividef(tn * s, mx_norm * SQRT_C);  // res = beta*(p*w)
    float res_norm = tn * (1.0f / SQRT_C);              // ||res||

    // project
    float rn = fmaxf(res_norm, MIN_N);
    float maxnorm = (1.0f - 0.001f) / SQRT_C;
    float gamma = (rn > maxnorm) ? __fdividef(maxnorm, rn) : 1.0f;

    // logmap0
    float y_norm = fmaxf(gamma * res_norm, MIN_N);
    float cy = fminf(fmaxf(SQRT_C * y_norm, -1.0f + EPS), 1.0f - EPS);
    float at2 = fast_atanh01(cy);
    float alpha = __fdividef(gamma * beta * at2, y_norm * SQRT_C);

    float4* __restrict__ orow = reinterpret_cast<float4*>(out) +
                                (size_t)warp_global * (NCOLS / 4);
#pragma unroll
    for (int j = 0; j < 4; ++j) {
        float4 o;
        o.x = alpha * m[j].x;
        o.y = alpha * m[j].y;
        o.z = alpha * m[j].z;
        o.w = alpha * m[j].w;
        orow[j * 32 + lane] = o;
    }
}

extern "C" void kernel_launch(void* const* d_in, const int* in_sizes, int n_in,
                              void* d_out, int out_size)
{
    const float* params  = (const float*)d_in[0];
    const float* weights = (const float*)d_in[1];
    float* out = (float*)d_out;

    int nrows = in_sizes[0] / NCOLS;   // 131072
    int blocks = (nrows + WARPS_PER_BLOCK - 1) / WARPS_PER_BLOCK;

    hyp_adapter_kernel<<<blocks, WARPS_PER_BLOCK * 32>>>(params, weights, out, nrows);
}